// round 2
// baseline (speedup 1.0000x reference)
#include <cuda_runtime.h>
#include <cstdint>

#define P 68          // smem row pitch (floats)
#define KH 20         // half window
#define WROWS 112     // window rows kept in smem (104 needed + 8 pad for block overcompute)

__device__ float g_C[16*64*64];
__device__ float g_cb[16*64];
__device__ float g_d[16*64];
__device__ float g_e[16];

// ---------------------------------------------------------------------------
// Precompute: C = Wq^T Wk, cb = bq.Wk, d = Wq^T bk, e = bq.bk  (per al)
// ---------------------------------------------------------------------------
__global__ __launch_bounds__(256) void precompute_kernel(
    const float* __restrict__ Wq, const float* __restrict__ bq,
    const float* __restrict__ Wk, const float* __restrict__ bk)
{
    __shared__ float sWq[64][65], sWk[64][65];
    __shared__ float sbq[64], sbk[64];
    int al = blockIdx.x, a = al >> 2, l = al & 3;
    size_t wb = ((size_t)(7 + a) * 5 + l) * 4096;
    size_t bb = ((size_t)(7 + a) * 5 + l) * 64;
    int t = threadIdx.x;
    for (int i = t; i < 4096; i += 256) {
        sWq[i >> 6][i & 63] = Wq[wb + i];
        sWk[i >> 6][i & 63] = Wk[wb + i];
    }
    if (t < 64) { sbq[t] = bq[bb + t]; sbk[t] = bk[bb + t]; }
    __syncthreads();

    int tf = t & 15, ts = t >> 4;
    float acc[4][4] = {};
    for (int g = 0; g < 64; g++) {
        float qv[4], kv[4];
#pragma unroll
        for (int i = 0; i < 4; i++) { qv[i] = sWq[g][ts*4+i]; kv[i] = sWk[g][tf*4+i]; }
#pragma unroll
        for (int i = 0; i < 4; i++)
#pragma unroll
            for (int j = 0; j < 4; j++) acc[i][j] += qv[i] * kv[j];
    }
#pragma unroll
    for (int i = 0; i < 4; i++)
#pragma unroll
        for (int j = 0; j < 4; j++)
            g_C[al*4096 + (ts*4+i)*64 + tf*4+j] = acc[i][j];

    if (t < 64) {
        float s = 0.f;
        for (int g = 0; g < 64; g++) s += sbq[g] * sWk[g][t];
        g_cb[al*64 + t] = s;
    } else if (t < 128) {
        int fi = t - 64; float s = 0.f;
        for (int g = 0; g < 64; g++) s += sWq[g][fi] * sbk[g];
        g_d[al*64 + fi] = s;
    } else if (t == 128) {
        float s = 0.f;
        for (int g = 0; g < 64; g++) s += sbq[g] * sbk[g];
        g_e[al] = s;
    }
}

// ---------------------------------------------------------------------------
// Fused attention: grid = 16(al) * 4(b) * 32(s-tiles of 64), 256 threads
// ---------------------------------------------------------------------------
__global__ __launch_bounds__(256, 2) void attn_kernel(
    const float* __restrict__ X, const float* __restrict__ Wt,
    const float* __restrict__ bt, float* __restrict__ out)
{
    extern __shared__ float sm[];
    float* sWin  = sm;                   // WROWS*P, chunk-swizzled
    float* sU    = sWin + WROWS*P;       // 64*P (U, later ctx)
    float* sC    = sU   + 64*P;          // 64*P
    float* sWtt  = sC   + 64*P;          // 64*P (Wt transposed [f][g])
    float* sAttn = sWtt + 64*P;          // 64*P
    float* sFlag = sAttn + 64*P;         // 104
    float* sBias = sFlag + 104;          // 64
    float* sBt   = sBias + 64;           // 64
    float* scb   = sBt  + 64;            // 64
    float* sd    = scb  + 64;            // 64

    int bx = blockIdx.x;
    int st = bx & 31, b = (bx >> 5) & 3, al = bx >> 7;
    int a = al >> 2, l = al & 3;
    int s0 = st * 64;
    int t = threadIdx.x;

    // ---- loads ----
    for (int q = t; q < WROWS*16; q += 256) {
        int r = q >> 4, c4 = q & 15;
        int sg = s0 - KH + r;
        float4 v = make_float4(0.f, 0.f, 0.f, 0.f);
        if (sg >= 0 && sg < 2048)
            v = *(const float4*)&X[(((size_t)b*2048 + sg)*4 + a)*64 + c4*4];
        int ch = (c4 + (r >> 2)) & 15;
        *(float4*)&sWin[r*P + ch*4] = v;
    }
    for (int q = t; q < 1024; q += 256) {
        int r = q >> 4, c4 = (q & 15) * 4;
        *(float4*)&sC[r*P + c4] = *(const float4*)&g_C[al*4096 + r*64 + c4];
    }
    size_t wb = ((size_t)(7 + a) * 5 + l) * 4096;
    for (int q = t; q < 4096; q += 256) {
        int g = q >> 6, f = q & 63;
        sWtt[f*P + g] = Wt[wb + q];
    }
    if (t < 64) {
        scb[t] = g_cb[al*64 + t];
        sd[t]  = g_d[al*64 + t];
        sBt[t] = bt[((7 + a)*5 + l)*64 + t];
    }
    __syncthreads();

    // ---- zero-row flags (rows 0..103) ----
    if (t < 104) {
        bool nz = false;
        int rq = t >> 2;
        for (int c4 = 0; c4 < 16; c4++) {
            int ch = (c4 + rq) & 15;
            float4 v = *(float4*)&sWin[t*P + ch*4];
            nz = nz || v.x != 0.f || v.y != 0.f || v.z != 0.f || v.w != 0.f;
        }
        sFlag[t] = nz ? 1.f : 0.f;
    }

    // ---- U = Xc*C + cb  (Xc = sWin rows 20..83) ----
    {
        int tf = t & 15, ts = t >> 4;
        int fo0 = tf * 4;
        float acc[4][4] = {};
#pragma unroll 4
        for (int fi = 0; fi < 64; fi += 4) {
            float4 cv0 = *(float4*)&sC[(fi+0)*P + fo0];
            float4 cv1 = *(float4*)&sC[(fi+1)*P + fo0];
            float4 cv2 = *(float4*)&sC[(fi+2)*P + fo0];
            float4 cv3 = *(float4*)&sC[(fi+3)*P + fo0];
#pragma unroll
            for (int i = 0; i < 4; i++) {
                int r = KH + ts*4 + i;
                int ch = ((fi >> 2) + (r >> 2)) & 15;
                float4 xv = *(float4*)&sWin[r*P + ch*4];
                acc[i][0] += xv.x*cv0.x + xv.y*cv1.x + xv.z*cv2.x + xv.w*cv3.x;
                acc[i][1] += xv.x*cv0.y + xv.y*cv1.y + xv.z*cv2.y + xv.w*cv3.y;
                acc[i][2] += xv.x*cv0.z + xv.y*cv1.z + xv.z*cv2.z + xv.w*cv3.z;
                acc[i][3] += xv.x*cv0.w + xv.y*cv1.w + xv.z*cv2.w + xv.w*cv3.w;
            }
        }
#pragma unroll
        for (int i = 0; i < 4; i++) {
            float4 o = make_float4(acc[i][0]+scb[fo0], acc[i][1]+scb[fo0+1],
                                   acc[i][2]+scb[fo0+2], acc[i][3]+scb[fo0+3]);
            *(float4*)&sU[(ts*4+i)*P + fo0] = o;
        }
    }
    // ---- bias_q = Xc_q . d + e ----
    if (t < 64) {
        int r = KH + t, rq = r >> 2;
        float s = 0.f;
        for (int c = 0; c < 64; c++) {
            int ch = ((c >> 2) + rq) & 15;
            s += sWin[r*P + ch*4 + (c & 3)] * sd[c];
        }
        sBias[t] = s + g_e[al];
    }
    __syncthreads();

    // ---- banded scores: per 16-query block vs 64 window rows ----
    {
        int sb = t >> 6, tt = t & 63;
        int trr = tt & 15, tss = tt >> 4;
        int R0 = sb * 16;
        float acc[4][4] = {};
#pragma unroll 4
        for (int fi = 0; fi < 64; fi += 4) {
            float4 wv[4];
#pragma unroll
            for (int j = 0; j < 4; j++) {
                int r = R0 + trr*4 + j;
                int ch = ((fi >> 2) + (r >> 2)) & 15;
                wv[j] = *(float4*)&sWin[r*P + ch*4];
            }
#pragma unroll
            for (int i = 0; i < 4; i++) {
                float4 xv = *(float4*)&sU[(R0 + tss*4 + i)*P + fi];
                acc[i][0] += xv.x*wv[0].x + xv.y*wv[0].y + xv.z*wv[0].z + xv.w*wv[0].w;
                acc[i][1] += xv.x*wv[1].x + xv.y*wv[1].y + xv.z*wv[1].z + xv.w*wv[1].w;
                acc[i][2] += xv.x*wv[2].x + xv.y*wv[2].y + xv.z*wv[2].z + xv.w*wv[2].w;
                acc[i][3] += xv.x*wv[3].x + xv.y*wv[3].y + xv.z*wv[3].z + xv.w*wv[3].w;
            }
        }
#pragma unroll
        for (int i = 0; i < 4; i++)
            *(float4*)&sAttn[(R0 + tss*4 + i)*P + trr*4] =
                make_float4(acc[i][0], acc[i][1], acc[i][2], acc[i][3]);
    }
    __syncthreads();

    // ---- softmax (one thread per query) ----
    if (t < 64) {
        int srem = t & 15;
        float* row = &sAttn[t*P];
        float bias = sBias[t];
        float m = -1e30f;
        for (int j = 0; j <= 40; j++) {
            float v = (row[srem + j] + bias) * 0.125f;
            if (sFlag[t + j] == 0.f) v = -1e9f;
            row[srem + j] = v;
            m = fmaxf(m, v);
        }
        float ssum = 0.f;
        for (int j = 0; j <= 40; j++) {
            float e = __expf(row[srem + j] - m);
            row[srem + j] = e;
            ssum += e;
        }
        float inv = 1.f / ssum;
        for (int rr = 0; rr < 64; rr++) {
            float wv = (rr >= srem && rr <= srem + 40) ? row[rr] * inv : 0.f;
            row[rr] = wv;
        }
    }
    __syncthreads();

    // ---- ctx = wgt * win (into sU) ----
    {
        int sb = t >> 6, tt = t & 63;
        int tf = tt & 15, tss = tt >> 4;
        int R0 = sb * 16;
        int f0 = tf * 4;
        float acc[4][4] = {};
#pragma unroll 4
        for (int rr = 0; rr < 64; rr += 4) {
            float4 wg[4];
#pragma unroll
            for (int i = 0; i < 4; i++)
                wg[i] = *(float4*)&sAttn[(R0 + tss*4 + i)*P + rr];
            float4 wv[4];
#pragma unroll
            for (int j = 0; j < 4; j++) {
                int r = R0 + rr + j;
                int ch = ((f0 >> 2) + (r >> 2)) & 15;
                wv[j] = *(float4*)&sWin[r*P + ch*4];
            }
#pragma unroll
            for (int i = 0; i < 4; i++) {
                acc[i][0] += wg[i].x*wv[0].x + wg[i].y*wv[1].x + wg[i].z*wv[2].x + wg[i].w*wv[3].x;
                acc[i][1] += wg[i].x*wv[0].y + wg[i].y*wv[1].y + wg[i].z*wv[2].y + wg[i].w*wv[3].y;
                acc[i][2] += wg[i].x*wv[0].z + wg[i].y*wv[1].z + wg[i].z*wv[2].z + wg[i].w*wv[3].z;
                acc[i][3] += wg[i].x*wv[0].w + wg[i].y*wv[1].w + wg[i].z*wv[2].w + wg[i].w*wv[3].w;
            }
        }
#pragma unroll
        for (int i = 0; i < 4; i++)
            *(float4*)&sU[(R0 + tss*4 + i)*P + f0] =
                make_float4(acc[i][0], acc[i][1], acc[i][2], acc[i][3]);
    }
    __syncthreads();

    // ---- out = ctx * Wt^T + bt ----
    {
        int tf = t & 15, ts = t >> 4;
        int g0 = tf * 4;
        float acc[4][4] = {};
#pragma unroll 4
        for (int f = 0; f < 64; f += 4) {
            float4 cv0 = *(float4*)&sWtt[(f+0)*P + g0];
            float4 cv1 = *(float4*)&sWtt[(f+1)*P + g0];
            float4 cv2 = *(float4*)&sWtt[(f+2)*P + g0];
            float4 cv3 = *(float4*)&sWtt[(f+3)*P + g0];
#pragma unroll
            for (int i = 0; i < 4; i++) {
                float4 xv = *(float4*)&sU[(ts*4+i)*P + f];
                acc[i][0] += xv.x*cv0.x + xv.y*cv1.x + xv.z*cv2.x + xv.w*cv3.x;
                acc[i][1] += xv.x*cv0.y + xv.y*cv1.y + xv.z*cv2.y + xv.w*cv3.y;
                acc[i][2] += xv.x*cv0.z + xv.y*cv1.z + xv.z*cv2.z + xv.w*cv3.z;
                acc[i][3] += xv.x*cv0.w + xv.y*cv1.w + xv.z*cv2.w + xv.w*cv3.w;
            }
        }
#pragma unroll
        for (int i = 0; i < 4; i++) {
            int q = ts*4 + i;
            size_t idx = ((((size_t)b*2048 + s0 + q)*4 + a)*4 + l)*64 + g0;
            float4 o = make_float4(acc[i][0]+sBt[g0], acc[i][1]+sBt[g0+1],
                                   acc[i][2]+sBt[g0+2], acc[i][3]+sBt[g0+3]);
            *(float4*)&out[idx] = o;
        }
    }
}

#define SMEM_BYTES ((WROWS*P + 4*64*P + 104 + 4*64) * 4)

extern "C" void kernel_launch(void* const* d_in, const int* in_sizes, int n_in,
                              void* d_out, int out_size) {
    (void)in_sizes; (void)n_in; (void)out_size;
    const float* X  = (const float*)d_in[0];
    const float* Wq = (const float*)d_in[1];
    const float* bq = (const float*)d_in[2];
    const float* Wk = (const float*)d_in[3];
    const float* bk = (const float*)d_in[4];
    const float* Wt = (const float*)d_in[5];
    const float* bt = (const float*)d_in[6];
    float* out = (float*)d_out;

    cudaFuncSetAttribute(attn_kernel, cudaFuncAttributeMaxDynamicSharedMemorySize, SMEM_BYTES);
    precompute_kernel<<<16, 256>>>(Wq, bq, Wk, bk);
    attn_kernel<<<2048, 256, SMEM_BYTES>>>(X, Wt, bt, out);
}